// round 11
// baseline (speedup 1.0000x reference)
#include <cuda_runtime.h>
#include <cuda_fp16.h>
#include <cstdint>

#define IN_F  4096
#define OUT_F 4096
#define MTOT  2048

// fp16 scratch + sync state (device globals: no allocation in kernel_launch)
__device__ __half g_wh[(size_t)OUT_F * IN_F];   // w_q * s_w, [o, k] K-major
__device__ __half g_xh[(size_t)MTOT  * IN_F];   // permuted x, [m, k] K-major
__device__ unsigned g_cnt = 0;                  // barrier arrivals (self-resetting)
__device__ unsigned g_rel = 0;                  // barrier release epoch (monotonic)
__device__ unsigned g_wdone[32];                // per-k-group prep completion counters

static constexpr uint32_t TOTAL_CHUNKS = 8192u;       // 256 tiles x 32 k-iters
static constexpr uint32_t A_BYTES     = 65536;        // 2 x 32KB (kh halves)
static constexpr uint32_t STAGE_BYTES = 98304;
static constexpr uint32_t GEMM_SMEM   = 196608;

// ------------------------------------------------------------------ helpers
__device__ __forceinline__ uint32_t smem_u32(const void* p) {
    uint32_t a;
    asm("{ .reg .u64 t; cvta.to.shared.u64 t, %1; cvt.u32.u64 %0, t; }" : "=r"(a) : "l"(p));
    return a;
}
__device__ __forceinline__ uint32_t sw128(uint32_t off) { return off ^ ((off >> 3) & 0x70); }
__device__ __forceinline__ void cpa16(uint32_t dst, const void* src) {
    asm volatile("cp.async.cg.shared.global [%0], [%1], 16;" :: "r"(dst), "l"(src));
}
__device__ __forceinline__ void redadd(float* p, float v) {
    asm volatile("red.global.add.f32 [%0], %1;" :: "l"(p), "f"(v) : "memory");
}
#define LDSM4(r0, r1, r2, r3, addr) \
    asm volatile("ldmatrix.sync.aligned.m8n8.x4.shared.b16 {%0,%1,%2,%3}, [%4];" \
        : "=r"(r0), "=r"(r1), "=r"(r2), "=r"(r3) : "r"(addr))
#define MMA16816(d0, d1, d2, d3, a0, a1, a2, a3, b0, b1) \
    asm volatile("mma.sync.aligned.m16n8k16.row.col.f32.f16.f16.f32 " \
        "{%0,%1,%2,%3},{%4,%5,%6,%7},{%8,%9},{%0,%1,%2,%3};" \
        : "+f"(d0), "+f"(d1), "+f"(d2), "+f"(d3) \
        : "r"(a0), "r"(a1), "r"(a2), "r"(a3), "r"(b0), "r"(b1))

// ---------------------------------------------------------- w-prep item (64B of wq)
__device__ __forceinline__ void wq_to_half(int4 wA, int4 wB, float s, uint4& v) {
    __half2 h0 = __floats2half2_rn(wA.x * s, wA.y * s);
    __half2 h1 = __floats2half2_rn(wA.z * s, wA.w * s);
    __half2 h2 = __floats2half2_rn(wB.x * s, wB.y * s);
    __half2 h3 = __floats2half2_rn(wB.z * s, wB.w * s);
    v.x = *reinterpret_cast<uint32_t*>(&h0);
    v.y = *reinterpret_cast<uint32_t*>(&h1);
    v.z = *reinterpret_cast<uint32_t*>(&h2);
    v.w = *reinterpret_cast<uint32_t*>(&h3);
}

// item u of group g: o = u>>3, seg = u&7 -> 16 cols [g*128+seg*16, +16)
__device__ __forceinline__ void prep_w_load(const int* __restrict__ wq,
                                            const float* __restrict__ sw,
                                            uint32_t g, uint32_t u0, uint32_t u1, int tid,
                                            int4& w0, int4& w1, int4& w2, int4& w3,
                                            float& s, uint32_t& off, bool& val) {
    uint32_t u = u0 + (uint32_t)tid;
    val = (u < u1);
    uint32_t o = u >> 3, seg = u & 7u;
    off = o * (uint32_t)IN_F + g * 128u + seg * 16u;
    if (val) {
        const int4* p = reinterpret_cast<const int4*>(wq + (size_t)off);
        w0 = __ldcs(p);     w1 = __ldcs(p + 1);
        w2 = __ldcs(p + 2); w3 = __ldcs(p + 3);
        s = sw[g * (uint32_t)OUT_F + o];
    }
}

__device__ __forceinline__ void prep_w_store(const int* __restrict__ wq,
                                             const float* __restrict__ sw,
                                             uint32_t g, uint32_t u0, uint32_t u1, int tid,
                                             int4 w0, int4 w1, int4 w2, int4 w3,
                                             float s, uint32_t off, bool val) {
    if (val) {
        uint4 v0, v1;
        wq_to_half(w0, w1, s, v0);
        wq_to_half(w2, w3, s, v1);
        uint4* dst = reinterpret_cast<uint4*>(g_wh + (size_t)off);
        __stcs(dst, v0);
        __stcs(dst + 1, v1);
    }
    // cold safety path: share larger than 256 items (only if nsm < 128)
    for (uint32_t u = u0 + 256u + (uint32_t)tid; u < u1; u += 256u) {
        uint32_t o = u >> 3, seg = u & 7u;
        uint32_t of2 = o * (uint32_t)IN_F + g * 128u + seg * 16u;
        const int4* p = reinterpret_cast<const int4*>(wq + (size_t)of2);
        int4 a0 = __ldcs(p), a1 = __ldcs(p + 1), a2 = __ldcs(p + 2), a3 = __ldcs(p + 3);
        float s2 = sw[g * (uint32_t)OUT_F + o];
        uint4 v0, v1;
        wq_to_half(a0, a1, s2, v0);
        wq_to_half(a2, a3, s2, v1);
        uint4* dst = reinterpret_cast<uint4*>(g_wh + (size_t)of2);
        __stcs(dst, v0);
        __stcs(dst + 1, v1);
    }
    __threadfence();   // make this thread's stores device-visible before publish
}

// ---------------------------------------------------------- GEMM pieces
__device__ __forceinline__ void load_chunk(uint32_t sb, uint32_t t, uint32_t k, int tid) {
    const int m0 = (int)(t >> 5) * 256;
    const int n0 = (int)(t & 31u) * 128;
    const int k0 = (int)k * 128;
#pragma unroll
    for (int kh = 0; kh < 2; ++kh) {
#pragma unroll
        for (int c = 0; c < 8; ++c) {             // A half: 256 rows x 8 chunks of 16B
            int idx = tid + c * 256;
            int row = idx >> 3, ch = idx & 7;
            cpa16(sb + (uint32_t)kh * 32768u + sw128((uint32_t)row * 128u + (uint32_t)ch * 16u),
                  g_xh + (size_t)(m0 + row) * IN_F + k0 + kh * 64 + ch * 8);
        }
#pragma unroll
        for (int c = 0; c < 4; ++c) {             // B half: 128 rows x 8 chunks
            int idx = tid + c * 256;
            int row = idx >> 3, ch = idx & 7;
            cpa16(sb + A_BYTES + (uint32_t)kh * 16384u + sw128((uint32_t)row * 128u + (uint32_t)ch * 16u),
                  g_wh + (size_t)(n0 + row) * IN_F + k0 + kh * 64 + ch * 8);
        }
    }
}

__device__ __forceinline__ void frag_load(uint32_t sA, uint32_t sB, int s,
                                          int arow_l, int a_c, int brow_l, int b_c,
                                          int wm, int wn, uint32_t a[4][4], uint32_t b[4][4]) {
    const uint32_t aBase = sA + (uint32_t)(s >> 2) * 32768u;
    const uint32_t bBase = sB + (uint32_t)(s >> 2) * 16384u;
    const int ks = s & 3;
#pragma unroll
    for (int mi = 0; mi < 4; ++mi) {
        uint32_t off = (uint32_t)((wm * 64 + mi * 16 + arow_l) * 128 + (ks * 2 + a_c) * 16);
        LDSM4(a[mi][0], a[mi][1], a[mi][2], a[mi][3], aBase + sw128(off));
    }
#pragma unroll
    for (int nb = 0; nb < 4; ++nb) {
        uint32_t off = (uint32_t)((wn * 64 + nb * 16 + brow_l) * 128 + (ks * 2 + b_c) * 16);
        LDSM4(b[nb][0], b[nb][1], b[nb][2], b[nb][3], bBase + sw128(off));
    }
}

__device__ __forceinline__ void frag_mma(const uint32_t a[4][4], const uint32_t b[4][4],
                                         float acc[4][8][4]) {
#pragma unroll
    for (int mi = 0; mi < 4; ++mi)
#pragma unroll
        for (int ni = 0; ni < 8; ++ni) {
            uint32_t b0 = b[ni >> 1][(ni & 1) * 2];
            uint32_t b1 = b[ni >> 1][(ni & 1) * 2 + 1];
            MMA16816(acc[mi][ni][0], acc[mi][ni][1], acc[mi][ni][2], acc[mi][ni][3],
                     a[mi][0], a[mi][1], a[mi][2], a[mi][3], b0, b1);
        }
}

// chunk i of the reordered per-CTA walk: head (t_last, 0..kb) -> fulls -> tail (t_first, ka..31)
__device__ __forceinline__ void chunk_at(uint32_t i, uint32_t Lh, uint32_t nf32,
                                         uint32_t t_last, uint32_t fstart,
                                         uint32_t t_first, uint32_t ka,
                                         uint32_t& t, uint32_t& k, bool& isfull) {
    if (i < Lh) { t = t_last; k = i; isfull = false; }
    else {
        uint32_t j = i - Lh;
        if (j < nf32) { t = fstart + (j >> 5); k = j & 31u; isfull = true; }
        else          { t = t_first; k = ka + (j - nf32); isfull = false; }
    }
}

// ---------------------------------------------------------- fused persistent kernel
__global__ void __launch_bounds__(256, 1) fused_kernel(const int* __restrict__ wq,
                                                       const float* __restrict__ sw,
                                                       const float* __restrict__ x,
                                                       const int* __restrict__ perm32,
                                                       const float* __restrict__ bias,
                                                       float* __restrict__ out,
                                                       int nsm_) {
    extern __shared__ char smem[];
    const uint32_t sbase = smem_u32(smem);
    const uint32_t nsm = (uint32_t)nsm_;
    const int tid  = threadIdx.x;
    const int lane = tid & 31, wid = tid >> 5;
    const int wm = wid & 3, wn = wid >> 2;        // 4 x 2 warp grid, warp tile 64x64
    const int arow_l = (lane & 7) + ((lane >> 3) & 1) * 8;
    const int a_c    = lane >> 4;
    const int brow_l = (lane & 7) + ((lane >> 4) & 1) * 8;
    const int b_c    = (lane >> 3) & 1;
    const uint32_t cta = blockIdx.x;

    __shared__ int is64s;

    // ================= Phase A: xh prep + split-tile prefill + flag reset =================
    if (tid == 0 && cta < 32u) g_wdone[cta] = 0u;
    if (tid == 0) {
        // jnp int64 vs int32 detection: int64 LE => odd 32-bit words all zero.
        int acc = 0;
#pragma unroll
        for (int t = 1; t < 32; t += 2) acc |= perm32[t];
        is64s = (acc == 0) ? 1 : 0;
    }
    __syncthreads();
    const int sh = is64s;
    float* rowbuf = reinterpret_cast<float*>(smem);     // 16KB of the GEMM smem

    for (uint32_t m = cta; m < MTOT; m += nsm) {
        const float4* src = reinterpret_cast<const float4*>(x + (size_t)m * IN_F);
#pragma unroll
        for (int i2 = 0; i2 < 4; ++i2)
            reinterpret_cast<float4*>(rowbuf)[tid + i2 * 256] = __ldcs(src + tid + i2 * 256);
        __syncthreads();
        const int j0 = tid * 16;
        __half* dst = g_xh + (size_t)m * IN_F + j0;
#pragma unroll
        for (int h = 0; h < 2; ++h) {
            int jb = j0 + h * 8;
            float v[8];
#pragma unroll
            for (int i2 = 0; i2 < 8; ++i2) v[i2] = rowbuf[perm32[(jb + i2) << sh]];
            __half2 p0 = __floats2half2_rn(v[0], v[1]);
            __half2 p1 = __floats2half2_rn(v[2], v[3]);
            __half2 p2 = __floats2half2_rn(v[4], v[5]);
            __half2 p3 = __floats2half2_rn(v[6], v[7]);
            uint4 u;
            u.x = *reinterpret_cast<uint32_t*>(&p0);
            u.y = *reinterpret_cast<uint32_t*>(&p1);
            u.z = *reinterpret_cast<uint32_t*>(&p2);
            u.w = *reinterpret_cast<uint32_t*>(&p3);
            __stcs(reinterpret_cast<uint4*>(dst + h * 8), u);
        }
        __syncthreads();
    }

    if (cta >= 1u) {                                    // prefill bias into my split tile
        uint32_t s = (cta * TOTAL_CHUNKS) / nsm;
        if (s & 31u) {
            uint32_t t = s >> 5;
            const int m0 = (int)(t >> 5) * 256, n0 = (int)(t & 31u) * 128;
            if (tid < 128) rowbuf[tid] = bias[n0 + tid];
            __syncthreads();
#pragma unroll 4
            for (int it = 0; it < 32; ++it) {
                int idx = tid + it * 256;
                int r = idx >> 5, c4 = idx & 31;
                float4 v = make_float4(rowbuf[c4 * 4], rowbuf[c4 * 4 + 1],
                                       rowbuf[c4 * 4 + 2], rowbuf[c4 * 4 + 3]);
                __stcs(reinterpret_cast<float4*>(out + (size_t)(m0 + r) * OUT_F + n0) + c4, v);
            }
        }
    }

    // grid barrier (all nsm CTAs resident: 1 CTA/SM). g_rel monotonic across graph replays.
    __threadfence();
    __syncthreads();
    if (tid == 0) {
        unsigned rel0 = atomicAdd(&g_rel, 0u);
        unsigned old  = atomicAdd(&g_cnt, 1u);
        if (old == nsm - 1u) { g_cnt = 0u; __threadfence(); atomicAdd(&g_rel, 1u); }
        else { while (atomicAdd(&g_rel, 0u) == rel0) __nanosleep(128); }
        __threadfence();
    }
    __syncthreads();

    // ================= Phase B: GEMM with pipelined w-prep =================
    const uint32_t start = (cta * TOTAL_CHUNKS) / nsm;
    const uint32_t end   = ((cta + 1u) * TOTAL_CHUNKS) / nsm;
    const uint32_t n_it  = end - start;
    const uint32_t ka = start & 31u, kb = end & 31u;
    const uint32_t t_first = start >> 5, t_last = end >> 5;
    const uint32_t Lh = kb;                                    // head length (0 if none)
    const uint32_t fstart = t_first + (ka ? 1u : 0u);
    const uint32_t nf32 = (t_last - fstart) * 32u;
    const uint32_t u0 = (cta * 32768u) / nsm, u1 = ((cta + 1u) * 32768u) / nsm;

    // pre-prep k-groups 0 and 1 (latency exposed; startup only)
    {
        int4 a0, a1, a2, a3; float s; uint32_t off; bool v;
        prep_w_load(wq, sw, 0u, u0, u1, tid, a0, a1, a2, a3, s, off, v);
        prep_w_store(wq, sw, 0u, u0, u1, tid, a0, a1, a2, a3, s, off, v);
        prep_w_load(wq, sw, 1u, u0, u1, tid, a0, a1, a2, a3, s, off, v);
        prep_w_store(wq, sw, 1u, u0, u1, tid, a0, a1, a2, a3, s, off, v);
    }
    __syncthreads();
    if (tid == 0) {
        atomicAdd(&g_wdone[0], 1u);
        atomicAdd(&g_wdone[1], 1u);
        while (atomicAdd(&g_wdone[0], 0u) < nsm) __nanosleep(128);   // gate k=0
    }
    __syncthreads();

    uint32_t ct, ck; bool cfull;
    chunk_at(0u, Lh, nf32, t_last, fstart, t_first, ka, ct, ck, cfull);   // ck == 0
    load_chunk(sbase, ct, ck, tid);
    asm volatile("cp.async.commit_group;" ::: "memory");

    float acc[4][8][4];
#pragma unroll
    for (int i = 0; i < 4; ++i)
#pragma unroll
        for (int j = 0; j < 8; ++j)
#pragma unroll
            for (int q = 0; q < 4; ++q) acc[i][j][q] = 0.f;

    uint32_t afrag[2][4][4], bfrag[2][4][4];
    int4 pw0, pw1, pw2, pw3; float ps = 0.f; uint32_t poff = 0; bool pval = false;
    uint32_t kok = 1u;                          // k-groups < kok verified globally done

    for (uint32_t i = 0; i < n_it; ++i) {
        const uint32_t gld = i + 2u;            // group loaded now, stored at loop bottom
        if (gld < 32u)
            prep_w_load(wq, sw, gld, u0, u1, tid, pw0, pw1, pw2, pw3, ps, poff, pval);

        asm volatile("cp.async.wait_group 0;" ::: "memory");
        __syncthreads();

        uint32_t nt = 0, nk = 0; bool nfull = false;
        const bool havenext = (i + 1u < n_it);
        if (havenext)
            chunk_at(i + 1u, Lh, nf32, t_last, fstart, t_first, ka, nt, nk, nfull);
        if (tid == 0) {
            if (i >= 1u && (i + 1u) < 32u) atomicAdd(&g_wdone[i + 1u], 1u);   // publish
            if (havenext) {
                while (nk >= kok) {                                            // gate
                    if (atomicAdd(&g_wdone[nk], 0u) >= nsm) kok = nk + 1u;
                    else __nanosleep(128);
                }
            }
        }
        __syncthreads();

        const uint32_t sA = sbase + (i & 1u) * STAGE_BYTES;
        const uint32_t sB = sA + A_BYTES;
        frag_load(sA, sB, 0, arow_l, a_c, brow_l, b_c, wm, wn, afrag[0], bfrag[0]);

        if (havenext)
            load_chunk(sbase + ((i + 1u) & 1u) * STAGE_BYTES, nt, nk, tid);
        asm volatile("cp.async.commit_group;" ::: "memory");

#pragma unroll
        for (int s = 0; s < 8; ++s) {
            if (s < 7)
                frag_load(sA, sB, s + 1, arow_l, a_c, brow_l, b_c, wm, wn,
                          afrag[(s + 1) & 1], bfrag[(s + 1) & 1]);
            frag_mma(afrag[s & 1], bfrag[s & 1], acc);
        }

        if (gld < 32u)                          // convert+store group gld (loads long ready)
            prep_w_store(wq, sw, gld, u0, u1, tid, pw0, pw1, pw2, pw3, ps, poff, pval);

        const bool tdone = (ck == 31u) || (i + 1u == Lh);
        if (tdone) {
            const int n0 = (int)(ct & 31u) * 128;
            const int m0 = (int)(ct >> 5) * 256;
            const int ncol = n0 + wn * 64 + (lane & 3) * 2;
            const int mrow = m0 + wm * 64 + (lane >> 2);
            if (cfull) {                        // sole writer: direct store with bias
#pragma unroll
                for (int mi = 0; mi < 4; ++mi) {
                    float* r0 = out + (size_t)(mrow + mi * 16) * OUT_F;
                    float* r1 = r0 + 8 * OUT_F;
#pragma unroll
                    for (int ni = 0; ni < 8; ++ni) {
                        float2 bv = *reinterpret_cast<const float2*>(bias + ncol + ni * 8);
                        float2 v0, v1;
                        v0.x = acc[mi][ni][0] + bv.x;
                        v0.y = acc[mi][ni][1] + bv.y;
                        v1.x = acc[mi][ni][2] + bv.x;
                        v1.y = acc[mi][ni][3] + bv.y;
                        *reinterpret_cast<float2*>(r0 + ncol + ni * 8) = v0;
                        *reinterpret_cast<float2*>(r1 + ncol + ni * 8) = v1;
                    }
                }
            } else {                            // split tile: accumulate into prefilled out
#pragma unroll
                for (int mi = 0; mi < 4; ++mi) {
                    float* r0 = out + (size_t)(mrow + mi * 16) * OUT_F;
                    float* r1 = r0 + 8 * OUT_F;
#pragma unroll
                    for (int ni = 0; ni < 8; ++ni) {
                        redadd(r0 + ncol + ni * 8,     acc[mi][ni][0]);
                        redadd(r0 + ncol + ni * 8 + 1, acc[mi][ni][1]);
                        redadd(r1 + ncol + ni * 8,     acc[mi][ni][2]);
                        redadd(r1 + ncol + ni * 8 + 1, acc[mi][ni][3]);
                    }
                }
            }
#pragma unroll
            for (int i2 = 0; i2 < 4; ++i2)
#pragma unroll
                for (int j = 0; j < 8; ++j)
#pragma unroll
                    for (int q = 0; q < 4; ++q) acc[i2][j][q] = 0.f;
        }
        if (havenext) { ct = nt; ck = nk; cfull = nfull; }
    }
}

// ---------------------------------------------------------- launch
extern "C" void kernel_launch(void* const* d_in, const int* in_sizes, int n_in,
                              void* d_out, int out_size) {
    const float* x    = (const float*)d_in[0];
    const int*   wq   = (const int*)d_in[1];
    const float* sw   = (const float*)d_in[2];
    const int*   perm = (const int*)d_in[3];   // int32 or int64 — detected on device
    const float* bias = (const float*)d_in[4];
    float* out = (float*)d_out;

    int nsm = 148;
    cudaDeviceGetAttribute(&nsm, cudaDevAttrMultiProcessorCount, 0);

    cudaFuncSetAttribute(fused_kernel, cudaFuncAttributeMaxDynamicSharedMemorySize, GEMM_SMEM);
    fused_kernel<<<nsm, 256, GEMM_SMEM>>>(wq, sw, x, perm, bias, out, nsm);
}

// round 12
// speedup vs baseline: 1.3711x; 1.3711x over previous
#include <cuda_runtime.h>
#include <cuda_fp16.h>
#include <cstdint>

#define IN_F  4096
#define OUT_F 4096
#define MTOT  2048

// fp16 scratch (device globals: no allocation in kernel_launch)
__device__ __half g_xh[(size_t)MTOT * IN_F];    // permuted x, [m, k] K-major

static constexpr uint32_t TOTAL_CHUNKS = 16384u;  // 256 tiles x 64 k-iters (BK=64)
static constexpr uint32_t GEMM_SMEM    = 98304;   // A 2x32KB + B(fp16) 2x16KB

// ------------------------------------------------------------------ helpers
__device__ __forceinline__ uint32_t smem_u32(const void* p) {
    uint32_t a;
    asm("{ .reg .u64 t; cvta.to.shared.u64 t, %1; cvt.u32.u64 %0, t; }" : "=r"(a) : "l"(p));
    return a;
}
__device__ __forceinline__ uint32_t sw128(uint32_t off) { return off ^ ((off >> 3) & 0x70); }
__device__ __forceinline__ void cpa16(uint32_t dst, const void* src) {
    asm volatile("cp.async.cg.shared.global [%0], [%1], 16;" :: "r"(dst), "l"(src));
}
__device__ __forceinline__ void redadd(float* p, float v) {
    asm volatile("red.global.add.f32 [%0], %1;" :: "l"(p), "f"(v) : "memory");
}
#define STS64(addr, v0, v1) \
    asm volatile("st.shared.v2.u32 [%0], {%1,%2};" :: "r"(addr), "r"(v0), "r"(v1) : "memory")
#define LDSM4(r0, r1, r2, r3, addr) \
    asm volatile("ldmatrix.sync.aligned.m8n8.x4.shared.b16 {%0,%1,%2,%3}, [%4];" \
        : "=r"(r0), "=r"(r1), "=r"(r2), "=r"(r3) : "r"(addr))
#define MMA16816(d0, d1, d2, d3, a0, a1, a2, a3, b0, b1) \
    asm volatile("mma.sync.aligned.m16n8k16.row.col.f32.f16.f16.f32 " \
        "{%0,%1,%2,%3},{%4,%5,%6,%7},{%8,%9},{%0,%1,%2,%3};" \
        : "+f"(d0), "+f"(d1), "+f"(d2), "+f"(d3) \
        : "r"(a0), "r"(a1), "r"(a2), "r"(a3), "r"(b0), "r"(b1))

// ---------------------------------------------------------- prep: x permute + split prefill
// blocks [0, 2048):  x-row m; permute + fp32->fp16
// blocks [2048, ..): boundary c = bid-2048+1; prefill bias into SPLIT tiles only
__global__ void __launch_bounds__(256) prep_kernel(const float* __restrict__ x,
                                                   const int* __restrict__ perm32,
                                                   const float* __restrict__ bias,
                                                   float* __restrict__ out,
                                                   int nsm_) {
    __shared__ float row[IN_F];
    __shared__ int is64s;
    const int tid = threadIdx.x;
    const uint32_t nsm = (uint32_t)nsm_;

    if (blockIdx.x >= 2048) {            // split-tile bias prefill
        const uint32_t c = blockIdx.x - 2048u + 1u;
        const uint32_t s = (c * TOTAL_CHUNKS) / nsm;
        if ((s & 63u) == 0u) return;
        const uint32_t t = s >> 6;
        const int m0 = (int)(t >> 5) * 256, n0 = (int)(t & 31u) * 128;
        if (tid < 128) row[tid] = bias[n0 + tid];
        __syncthreads();
#pragma unroll 4
        for (int it = 0; it < 32; ++it) {
            int idx = tid + it * 256;
            int r = idx >> 5, c4 = idx & 31;
            float4 v = make_float4(row[c4 * 4], row[c4 * 4 + 1], row[c4 * 4 + 2], row[c4 * 4 + 3]);
            __stcs(reinterpret_cast<float4*>(out + (size_t)(m0 + r) * OUT_F + n0) + c4, v);
        }
        return;
    }

    const int m = blockIdx.x;
    const float4* src = reinterpret_cast<const float4*>(x + (size_t)m * IN_F);
#pragma unroll
    for (int i = 0; i < 4; ++i)
        reinterpret_cast<float4*>(row)[tid + i * 256] = __ldcs(src + tid + i * 256);
    if (tid == 0) {
        // jnp int64 vs int32 detection: int64 LE => odd 32-bit words all zero.
        int acc = 0;
#pragma unroll
        for (int t = 1; t < 32; t += 2) acc |= perm32[t];
        is64s = (acc == 0) ? 1 : 0;
    }
    __syncthreads();
    const int sh = is64s;
    const int j0 = tid * 16;
    __half* dst = g_xh + (size_t)m * IN_F + j0;
#pragma unroll
    for (int h = 0; h < 2; ++h) {
        int jb = j0 + h * 8;
        float v[8];
#pragma unroll
        for (int i = 0; i < 8; ++i) v[i] = row[perm32[(jb + i) << sh]];
        __half2 p0 = __floats2half2_rn(v[0], v[1]);
        __half2 p1 = __floats2half2_rn(v[2], v[3]);
        __half2 p2 = __floats2half2_rn(v[4], v[5]);
        __half2 p3 = __floats2half2_rn(v[6], v[7]);
        uint4 u;
        u.x = *reinterpret_cast<uint32_t*>(&p0);
        u.y = *reinterpret_cast<uint32_t*>(&p1);
        u.z = *reinterpret_cast<uint32_t*>(&p2);
        u.w = *reinterpret_cast<uint32_t*>(&p3);
        __stcs(reinterpret_cast<uint4*>(dst + h * 8), u);
    }
}

// ---------------------------------------------------------- GEMM with in-loop B dequant
// Tile 256(M) x 128(N) x 64(BK); chunk = one k-iter; 16384 chunks over nsm persistent CTAs.
// A: cp.async fp16 from g_xh, 2 slots. B: per-iter register dequant of wq int32 (one
// iteration ahead) -> STS into fp16 tile, 2 slots. All ordering is CTA-local syncs.
__device__ __forceinline__ void loadA(uint32_t sb, uint32_t ch, int tid,
                                      const __half* __restrict__ xh) {
    const uint32_t t = ch >> 6;
    const int m0 = (int)(t >> 5) * 256;
    const int k0 = (int)(ch & 63u) * 64;
#pragma unroll
    for (int c = 0; c < 8; ++c) {                 // 256 rows x 8 chunks of 16B
        int idx = tid + c * 256;
        int row = idx >> 3, cc = idx & 7;
        cpa16(sb + sw128((uint32_t)row * 128u + (uint32_t)cc * 16u),
              xh + (size_t)(m0 + row) * IN_F + k0 + cc * 8);
    }
}

// load one B chunk-batch (8 x int4 + 8 scales) for chunk ch
__device__ __forceinline__ void ldgB(const int* __restrict__ wq, const float* __restrict__ sw,
                                     uint32_t ch, int tid, int4 bw[8], float bs[8]) {
    const uint32_t t = ch >> 6;
    const int n0 = (int)(t & 31u) * 128;
    const int k  = (int)(ch & 63u);
    const int k0 = k * 64;
    const int g  = k >> 1;
#pragma unroll
    for (int j = 0; j < 8; ++j) {
        uint32_t q = (uint32_t)tid + (uint32_t)j * 256u;   // 2048 16B-chunks: row=q>>4, c16=q&15
        uint32_t row = q >> 4, c16 = q & 15u;
        bw[j] = *(reinterpret_cast<const int4*>(wq + (size_t)(n0 + row) * IN_F + k0) + c16);
        bs[j] = sw[(size_t)g * OUT_F + n0 + row];
    }
}

// convert + store into fp16 B tile (rows 128B, sw128)
__device__ __forceinline__ void stsB(uint32_t sB, int tid, const int4 bw[8], const float bs[8]) {
#pragma unroll
    for (int j = 0; j < 8; ++j) {
        uint32_t q = (uint32_t)tid + (uint32_t)j * 256u;
        uint32_t row = q >> 4, c16 = q & 15u;
        float s = bs[j];
        __half2 h0 = __floats2half2_rn(bw[j].x * s, bw[j].y * s);
        __half2 h1 = __floats2half2_rn(bw[j].z * s, bw[j].w * s);
        uint32_t addr = sB + sw128(row * 128u + c16 * 8u);
        STS64(addr, *reinterpret_cast<uint32_t*>(&h0), *reinterpret_cast<uint32_t*>(&h1));
    }
}

__device__ __forceinline__ void fragA(uint32_t sA, int ks, int arow_l, int a_c, int wm,
                                      uint32_t a[4][4]) {
#pragma unroll
    for (int mi = 0; mi < 4; ++mi) {
        uint32_t off = (uint32_t)((wm * 64 + mi * 16 + arow_l) * 128 + (ks * 2 + a_c) * 16);
        LDSM4(a[mi][0], a[mi][1], a[mi][2], a[mi][3], sA + sw128(off));
    }
}
__device__ __forceinline__ void fragB(uint32_t sB, int ks, int brow_l, int b_c, int wn,
                                      uint32_t b[4][4]) {
#pragma unroll
    for (int nb = 0; nb < 4; ++nb) {
        uint32_t off = (uint32_t)((wn * 64 + nb * 16 + brow_l) * 128 + (ks * 2 + b_c) * 16);
        LDSM4(b[nb][0], b[nb][1], b[nb][2], b[nb][3], sB + sw128(off));
    }
}
__device__ __forceinline__ void fragMMA(const uint32_t a[4][4], const uint32_t b[4][4],
                                        float acc[4][8][4]) {
#pragma unroll
    for (int mi = 0; mi < 4; ++mi)
#pragma unroll
        for (int ni = 0; ni < 8; ++ni) {
            uint32_t b0 = b[ni >> 1][(ni & 1) * 2];
            uint32_t b1 = b[ni >> 1][(ni & 1) * 2 + 1];
            MMA16816(acc[mi][ni][0], acc[mi][ni][1], acc[mi][ni][2], acc[mi][ni][3],
                     a[mi][0], a[mi][1], a[mi][2], a[mi][3], b0, b1);
        }
}

__global__ void __launch_bounds__(256, 1) gemm_kernel(const int* __restrict__ wq,
                                                      const float* __restrict__ sw,
                                                      const float* __restrict__ bias,
                                                      float* __restrict__ out,
                                                      int nsm_) {
    extern __shared__ char smem[];
    const uint32_t sbase = smem_u32(smem);
    const uint32_t nsm = (uint32_t)nsm_;
    const int tid  = threadIdx.x;
    const int lane = tid & 31, wid = tid >> 5;
    const int wm = wid & 3, wn = wid >> 2;        // 4 x 2 warp grid, warp tile 64x64
    const int arow_l = (lane & 7) + ((lane >> 3) & 1) * 8;
    const int a_c    = lane >> 4;
    const int brow_l = (lane & 7) + ((lane >> 4) & 1) * 8;
    const int b_c    = (lane >> 3) & 1;

    const uint32_t cta = blockIdx.x;
    const uint32_t start = (cta * TOTAL_CHUNKS) / nsm;
    const uint32_t end   = ((cta + 1u) * TOTAL_CHUNKS) / nsm;

    float acc[4][8][4];
#pragma unroll
    for (int i = 0; i < 4; ++i)
#pragma unroll
        for (int j = 0; j < 8; ++j)
#pragma unroll
            for (int q = 0; q < 4; ++q) acc[i][j][q] = 0.f;

    uint32_t abuf[2][4][4], bbuf[4][4];
    int4 bw[8]; float bs[8];
    uint32_t seg_first = start & 63u;

    // prologue: B(start) dequant -> slot, A(start) cp.async, B(start+1) regs
    ldgB(wq, sw, start, tid, bw, bs);
    stsB(sbase + 65536u + (start & 1u) * 16384u, tid, bw, bs);
    loadA(sbase + (start & 1u) * 32768u, start, tid, g_xh);
    asm volatile("cp.async.commit_group;" ::: "memory");
    if (start + 1u < end) ldgB(wq, sw, start + 1u, tid, bw, bs);

    for (uint32_t ch = start; ch < end; ++ch) {
        asm volatile("cp.async.wait_group 0;" ::: "memory");
        __syncthreads();                           // A(ch) + B(ch) fp16 visible to all

        const uint32_t sA = sbase + (ch & 1u) * 32768u;
        const uint32_t sB = sbase + 65536u + (ch & 1u) * 16384u;

        if (ch + 1u < end) {
            loadA(sbase + ((ch + 1u) & 1u) * 32768u, ch + 1u, tid, g_xh);
            asm volatile("cp.async.commit_group;" ::: "memory");
        }

        fragA(sA, 0, arow_l, a_c, wm, abuf[0]);
        fragB(sB, 0, brow_l, b_c, wn, bbuf);

        if (ch + 1u < end)                         // dequant next B into other slot
            stsB(sbase + 65536u + ((ch + 1u) & 1u) * 16384u, tid, bw, bs);
        if (ch + 2u < end)                         // prefetch B regs for next iter's dequant
            ldgB(wq, sw, ch + 2u, tid, bw, bs);

#pragma unroll
        for (int s = 0; s < 4; ++s) {
            if (s < 3) fragA(sA, s + 1, arow_l, a_c, wm, abuf[(s + 1) & 1]);
            fragMMA(abuf[s & 1], bbuf, acc);
            if (s < 3) fragB(sB, s + 1, brow_l, b_c, wn, bbuf);
        }

        const uint32_t kidx = ch & 63u;
        const bool tile_done = (kidx == 63u) || (ch + 1u == end);
        if (tile_done) {
            const uint32_t t = ch >> 6;
            const int n0 = (int)(t & 31u) * 128;
            const int m0 = (int)(t >> 5) * 256;
            const int ncol = n0 + wn * 64 + (lane & 3) * 2;
            const int mrow = m0 + wm * 64 + (lane >> 2);
            const bool full = (seg_first == 0u && kidx == 63u);
            if (full) {
#pragma unroll
                for (int mi = 0; mi < 4; ++mi) {
                    float* r0 = out + (size_t)(mrow + mi * 16) * OUT_F;
                    float* r1 = r0 + 8 * OUT_F;
#pragma unroll
                    for (int ni = 0; ni < 8; ++ni) {
                        float2 bv = *reinterpret_cast<const float2*>(bias + ncol + ni * 8);
                        float2 v0, v1;
                        v0.x = acc[mi][ni][0] + bv.x;
                        v0.y = acc[mi][ni][1] + bv.y;
                        v1.x = acc[mi][ni][2] + bv.x;
                        v1.y = acc[mi][ni][3] + bv.y;
                        *reinterpret_cast<float2*>(r0 + ncol + ni * 8) = v0;
                        *reinterpret_cast<float2*>(r1 + ncol + ni * 8) = v1;
                    }
                }
            } else {
#pragma unroll
                for (int mi = 0; mi < 4; ++mi) {
                    float* r0 = out + (size_t)(mrow + mi * 16) * OUT_F;
                    float* r1 = r0 + 8 * OUT_F;
#pragma unroll
                    for (int ni = 0; ni < 8; ++ni) {
                        redadd(r0 + ncol + ni * 8,     acc[mi][ni][0]);
                        redadd(r0 + ncol + ni * 8 + 1, acc[mi][ni][1]);
                        redadd(r1 + ncol + ni * 8,     acc[mi][ni][2]);
                        redadd(r1 + ncol + ni * 8 + 1, acc[mi][ni][3]);
                    }
                }
            }
#pragma unroll
            for (int i2 = 0; i2 < 4; ++i2)
#pragma unroll
                for (int j = 0; j < 8; ++j)
#pragma unroll
                    for (int q = 0; q < 4; ++q) acc[i2][j][q] = 0.f;
            seg_first = 0u;
        }
    }
}

// ---------------------------------------------------------- launch
extern "C" void kernel_launch(void* const* d_in, const int* in_sizes, int n_in,
                              void* d_out, int out_size) {
    const float* x    = (const float*)d_in[0];
    const int*   wq   = (const int*)d_in[1];
    const float* sw   = (const float*)d_in[2];
    const int*   perm = (const int*)d_in[3];   // int32 or int64 — detected on device
    const float* bias = (const float*)d_in[4];
    float* out = (float*)d_out;

    int nsm = 148;
    cudaDeviceGetAttribute(&nsm, cudaDevAttrMultiProcessorCount, 0);

    prep_kernel<<<2048 + nsm - 1, 256>>>(x, perm, bias, out, nsm);

    cudaFuncSetAttribute(gemm_kernel, cudaFuncAttributeMaxDynamicSharedMemorySize, GEMM_SMEM);
    gemm_kernel<<<nsm, 256, GEMM_SMEM>>>(wq, sw, bias, out, nsm);
}

// round 13
// speedup vs baseline: 1.6439x; 1.1990x over previous
#include <cuda_runtime.h>
#include <cuda_fp16.h>
#include <cstdint>

#define IN_F  4096
#define OUT_F 4096
#define MTOT  2048
#define NGRP  32          // IN_F / 128

// fp16 scratch (device globals: no allocation in kernel_launch)
__device__ __half g_wh[(size_t)OUT_F * IN_F];   // w_q * s_w, [o, k] K-major
__device__ __half g_xh[(size_t)MTOT  * IN_F];   // permuted x, [m, k] K-major

// Tile 128(M) x 128(N), BK = 64. 16 m-tiles x 32 n-tiles = 512 tiles x 64 k-iters.
static constexpr uint32_t TOTAL_CHUNKS = 32768u;
static constexpr uint32_t A_BYTES      = 16384;       // A 16KB + B 16KB per stage
static constexpr uint32_t STAGE_BYTES  = 32768;
static constexpr uint32_t GEMM_SMEM    = 3 * STAGE_BYTES;   // 96KB -> 2 CTAs/SM

// ------------------------------------------------------------------ helpers
__device__ __forceinline__ uint32_t smem_u32(const void* p) {
    uint32_t a;
    asm("{ .reg .u64 t; cvta.to.shared.u64 t, %1; cvt.u32.u64 %0, t; }" : "=r"(a) : "l"(p));
    return a;
}
__device__ __forceinline__ uint32_t sw128(uint32_t off) { return off ^ ((off >> 3) & 0x70); }
__device__ __forceinline__ void cpa16(uint32_t dst, const void* src) {
    asm volatile("cp.async.cg.shared.global [%0], [%1], 16;" :: "r"(dst), "l"(src));
}
__device__ __forceinline__ void redadd(float* p, float v) {
    asm volatile("red.global.add.f32 [%0], %1;" :: "l"(p), "f"(v) : "memory");
}
#define LDSM4(r0, r1, r2, r3, addr) \
    asm volatile("ldmatrix.sync.aligned.m8n8.x4.shared.b16 {%0,%1,%2,%3}, [%4];" \
        : "=r"(r0), "=r"(r1), "=r"(r2), "=r"(r3) : "r"(addr))
#define MMA16816(d0, d1, d2, d3, a0, a1, a2, a3, b0, b1) \
    asm volatile("mma.sync.aligned.m16n8k16.row.col.f32.f16.f16.f32 " \
        "{%0,%1,%2,%3},{%4,%5,%6,%7},{%8,%9},{%0,%1,%2,%3};" \
        : "+f"(d0), "+f"(d1), "+f"(d2), "+f"(d3) \
        : "r"(a0), "r"(a1), "r"(a2), "r"(a3), "r"(b0), "r"(b1))

// ---------------------------------------------------------- fused prep
// blocks [0, 4096):       w-row o; w_q * s_w -> fp16 (streaming hints)
// blocks [4096, 6144):    x-row m; permute + fp32->fp16
// blocks [6144, ...):     boundary c = bid-6144+1; prefill bias into SPLIT tiles only
__global__ void __launch_bounds__(256) prep_kernel(const int* __restrict__ wq,
                                                   const float* __restrict__ sw,
                                                   const float* __restrict__ x,
                                                   const int* __restrict__ perm32,
                                                   const float* __restrict__ bias,
                                                   float* __restrict__ out,
                                                   int ncta_) {
    __shared__ float row[IN_F];
    __shared__ int is64s;
    const int tid = threadIdx.x;
    const uint32_t ncta = (uint32_t)ncta_;

    if (blockIdx.x >= 6144) {            // split-tile bias prefill (128x128 tiles)
        const uint32_t c = blockIdx.x - 6144u + 1u;
        const uint32_t s = (c * TOTAL_CHUNKS) / ncta;
        if ((s & 63u) == 0u) return;
        const uint32_t t = s >> 6;
        const int m0 = (int)(t >> 5) * 128, n0 = (int)(t & 31u) * 128;
        if (tid < 128) row[tid] = bias[n0 + tid];
        __syncthreads();
#pragma unroll 4
        for (int it = 0; it < 16; ++it) {                 // 128 rows x 32 float4
            int idx = tid + it * 256;
            int r = idx >> 5, c4 = idx & 31;
            float4 v = make_float4(row[c4 * 4], row[c4 * 4 + 1], row[c4 * 4 + 2], row[c4 * 4 + 3]);
            __stcs(reinterpret_cast<float4*>(out + (size_t)(m0 + r) * OUT_F + n0) + c4, v);
        }
        return;
    }

    if (blockIdx.x < 4096) {
        const int o = blockIdx.x;
        if (tid < NGRP) row[tid] = sw[tid * OUT_F + o];
        __syncthreads();
        const float s = row[tid >> 3];
        const int k0 = tid * 16;
        const int4* p = reinterpret_cast<const int4*>(wq + (size_t)o * IN_F + k0);
        int4 w0 = __ldcs(p), w1 = __ldcs(p + 1), w2 = __ldcs(p + 2), w3 = __ldcs(p + 3);
        uint4 v0, v1;
        {
            __half2 h0 = __floats2half2_rn(w0.x * s, w0.y * s);
            __half2 h1 = __floats2half2_rn(w0.z * s, w0.w * s);
            __half2 h2 = __floats2half2_rn(w1.x * s, w1.y * s);
            __half2 h3 = __floats2half2_rn(w1.z * s, w1.w * s);
            v0.x = *reinterpret_cast<uint32_t*>(&h0);
            v0.y = *reinterpret_cast<uint32_t*>(&h1);
            v0.z = *reinterpret_cast<uint32_t*>(&h2);
            v0.w = *reinterpret_cast<uint32_t*>(&h3);
        }
        {
            __half2 h0 = __floats2half2_rn(w2.x * s, w2.y * s);
            __half2 h1 = __floats2half2_rn(w2.z * s, w2.w * s);
            __half2 h2 = __floats2half2_rn(w3.x * s, w3.y * s);
            __half2 h3 = __floats2half2_rn(w3.z * s, w3.w * s);
            v1.x = *reinterpret_cast<uint32_t*>(&h0);
            v1.y = *reinterpret_cast<uint32_t*>(&h1);
            v1.z = *reinterpret_cast<uint32_t*>(&h2);
            v1.w = *reinterpret_cast<uint32_t*>(&h3);
        }
        uint4* dst = reinterpret_cast<uint4*>(g_wh + (size_t)o * IN_F + k0);
        __stcs(dst, v0);
        __stcs(dst + 1, v1);
        return;
    }

    const int m = blockIdx.x - 4096;
    const float4* src = reinterpret_cast<const float4*>(x + (size_t)m * IN_F);
#pragma unroll
    for (int i = 0; i < 4; ++i)
        reinterpret_cast<float4*>(row)[tid + i * 256] = __ldcs(src + tid + i * 256);
    if (tid == 0) {
        // jnp int64 vs int32 detection: int64 LE => odd 32-bit words all zero.
        int acc = 0;
#pragma unroll
        for (int t = 1; t < 32; t += 2) acc |= perm32[t];
        is64s = (acc == 0) ? 1 : 0;
    }
    __syncthreads();
    const int sh = is64s;
    const int j0 = tid * 16;
    __half* dst = g_xh + (size_t)m * IN_F + j0;
#pragma unroll
    for (int h = 0; h < 2; ++h) {
        int jb = j0 + h * 8;
        float v[8];
#pragma unroll
        for (int i = 0; i < 8; ++i) v[i] = row[perm32[(jb + i) << sh]];
        __half2 p0 = __floats2half2_rn(v[0], v[1]);
        __half2 p1 = __floats2half2_rn(v[2], v[3]);
        __half2 p2 = __floats2half2_rn(v[4], v[5]);
        __half2 p3 = __floats2half2_rn(v[6], v[7]);
        uint4 u;
        u.x = *reinterpret_cast<uint32_t*>(&p0);
        u.y = *reinterpret_cast<uint32_t*>(&p1);
        u.z = *reinterpret_cast<uint32_t*>(&p2);
        u.w = *reinterpret_cast<uint32_t*>(&p3);
        __stcs(reinterpret_cast<uint4*>(dst + h * 8), u);
    }
}

// ---------------------------------------------------------- GEMM: persistent, 2 CTAs/SM
// 128 threads = 4 warps in 2(M) x 2(N), warp tile 64x64. 3-stage cp.async (96KB smem).
// 32768 chunks over 2*nsm CTAs (~108 each); flat chunk loop, cross-tile prefetch,
// red.global for split tiles (bias prefilled), direct store + bias for full tiles.
__device__ __forceinline__ void load_chunk(uint32_t sb, uint32_t chunk, int tid) {
    const uint32_t t = chunk >> 6;
    const int m0 = (int)(t >> 5) * 128;
    const int n0 = (int)(t & 31u) * 128;
    const int k0 = (int)(chunk & 63u) * 64;
#pragma unroll
    for (int c = 0; c < 8; ++c) {                 // A: 128 rows x 8 chunks of 16B
        int idx = tid + c * 128;
        int row = idx >> 3, ch = idx & 7;
        cpa16(sb + sw128((uint32_t)row * 128u + (uint32_t)ch * 16u),
              g_xh + (size_t)(m0 + row) * IN_F + k0 + ch * 8);
    }
#pragma unroll
    for (int c = 0; c < 8; ++c) {                 // B: 128 rows x 8 chunks
        int idx = tid + c * 128;
        int row = idx >> 3, ch = idx & 7;
        cpa16(sb + A_BYTES + sw128((uint32_t)row * 128u + (uint32_t)ch * 16u),
              g_wh + (size_t)(n0 + row) * IN_F + k0 + ch * 8);
    }
}

// Fragments for k-step s (0..3); warp tile 64(M) x 64(N)
__device__ __forceinline__ void frag_load(uint32_t sA, uint32_t sB, int s,
                                          int arow_l, int a_c, int brow_l, int b_c,
                                          int wm, int wn, uint32_t a[4][4], uint32_t b[4][4]) {
#pragma unroll
    for (int mi = 0; mi < 4; ++mi) {
        uint32_t off = (uint32_t)((wm * 64 + mi * 16 + arow_l) * 128 + (s * 2 + a_c) * 16);
        LDSM4(a[mi][0], a[mi][1], a[mi][2], a[mi][3], sA + sw128(off));
    }
#pragma unroll
    for (int nb = 0; nb < 4; ++nb) {
        uint32_t off = (uint32_t)((wn * 64 + nb * 16 + brow_l) * 128 + (s * 2 + b_c) * 16);
        LDSM4(b[nb][0], b[nb][1], b[nb][2], b[nb][3], sB + sw128(off));
    }
}

__device__ __forceinline__ void frag_mma(const uint32_t a[4][4], const uint32_t b[4][4],
                                         float acc[4][8][4]) {
#pragma unroll
    for (int mi = 0; mi < 4; ++mi)
#pragma unroll
        for (int ni = 0; ni < 8; ++ni) {
            uint32_t b0 = b[ni >> 1][(ni & 1) * 2];
            uint32_t b1 = b[ni >> 1][(ni & 1) * 2 + 1];
            MMA16816(acc[mi][ni][0], acc[mi][ni][1], acc[mi][ni][2], acc[mi][ni][3],
                     a[mi][0], a[mi][1], a[mi][2], a[mi][3], b0, b1);
        }
}

__global__ void __launch_bounds__(128, 2) gemm_kernel(const float* __restrict__ bias,
                                                      float* __restrict__ out,
                                                      int ncta_) {
    extern __shared__ char smem[];
    const uint32_t sbase = smem_u32(smem);
    const uint32_t ncta = (uint32_t)ncta_;
    const int tid  = threadIdx.x;
    const int lane = tid & 31, wid = tid >> 5;
    const int wm = wid & 1, wn = wid >> 1;        // 2 x 2 warp grid
    const int arow_l = (lane & 7) + ((lane >> 3) & 1) * 8;
    const int a_c    = lane >> 4;
    const int brow_l = (lane & 7) + ((lane >> 4) & 1) * 8;
    const int b_c    = (lane >> 3) & 1;

    const uint32_t cta = blockIdx.x;
    const uint32_t start = (cta * TOTAL_CHUNKS) / ncta;
    const uint32_t end   = ((cta + 1u) * TOTAL_CHUNKS) / ncta;

    float acc[4][8][4];
#pragma unroll
    for (int i = 0; i < 4; ++i)
#pragma unroll
        for (int j = 0; j < 8; ++j)
#pragma unroll
            for (int q = 0; q < 4; ++q) acc[i][j][q] = 0.f;

    uint32_t afrag[2][4][4], bfrag[2][4][4];
    uint32_t seg_first = start & 63u;

    // prologue: chunks start, start+1 (slot = chunk % 3)
    load_chunk(sbase + (start % 3u) * STAGE_BYTES, start, tid);
    asm volatile("cp.async.commit_group;" ::: "memory");
    if (start + 1u < end)
        load_chunk(sbase + ((start + 1u) % 3u) * STAGE_BYTES, start + 1u, tid);
    asm volatile("cp.async.commit_group;" ::: "memory");

    for (uint32_t ch = start; ch < end; ++ch) {
        asm volatile("cp.async.wait_group 1;" ::: "memory");
        __syncthreads();

        const uint32_t sA = sbase + (ch % 3u) * STAGE_BYTES;
        const uint32_t sB = sA + A_BYTES;

        // Step-0 fragments FIRST, so they aren't queued behind the LDGSTS burst.
        frag_load(sA, sB, 0, arow_l, a_c, brow_l, b_c, wm, wn, afrag[0], bfrag[0]);

        if (ch + 2u < end)
            load_chunk(sbase + ((ch + 2u) % 3u) * STAGE_BYTES, ch + 2u, tid);
        asm volatile("cp.async.commit_group;" ::: "memory");

#pragma unroll
        for (int s = 0; s < 4; ++s) {
            if (s < 3)
                frag_load(sA, sB, s + 1, arow_l, a_c, brow_l, b_c, wm, wn,
                          afrag[(s + 1) & 1], bfrag[(s + 1) & 1]);
            frag_mma(afrag[s & 1], bfrag[s & 1], acc);
        }

        const uint32_t kidx = ch & 63u;
        const bool tile_done = (kidx == 63u) || (ch + 1u == end);
        if (tile_done) {
            const uint32_t t = ch >> 6;
            const int n0 = (int)(t & 31u) * 128;
            const int m0 = (int)(t >> 5) * 128;
            const int ncol = n0 + wn * 64 + (lane & 3) * 2;
            const int mrow = m0 + wm * 64 + (lane >> 2);
            const bool full = (seg_first == 0u && kidx == 63u);
            if (full) {                           // sole writer: direct store with bias
#pragma unroll
                for (int mi = 0; mi < 4; ++mi) {
                    float* r0 = out + (size_t)(mrow + mi * 16) * OUT_F;
                    float* r1 = r0 + 8 * OUT_F;
#pragma unroll
                    for (int ni = 0; ni < 8; ++ni) {
                        float2 bv = *reinterpret_cast<const float2*>(bias + ncol + ni * 8);
                        float2 v0, v1;
                        v0.x = acc[mi][ni][0] + bv.x;
                        v0.y = acc[mi][ni][1] + bv.y;
                        v1.x = acc[mi][ni][2] + bv.x;
                        v1.y = acc[mi][ni][3] + bv.y;
                        *reinterpret_cast<float2*>(r0 + ncol + ni * 8) = v0;
                        *reinterpret_cast<float2*>(r1 + ncol + ni * 8) = v1;
                    }
                }
            } else {                              // split tile: accumulate into prefilled out
#pragma unroll
                for (int mi = 0; mi < 4; ++mi) {
                    float* r0 = out + (size_t)(mrow + mi * 16) * OUT_F;
                    float* r1 = r0 + 8 * OUT_F;
#pragma unroll
                    for (int ni = 0; ni < 8; ++ni) {
                        redadd(r0 + ncol + ni * 8,     acc[mi][ni][0]);
                        redadd(r0 + ncol + ni * 8 + 1, acc[mi][ni][1]);
                        redadd(r1 + ncol + ni * 8,     acc[mi][ni][2]);
                        redadd(r1 + ncol + ni * 8 + 1, acc[mi][ni][3]);
                    }
                }
            }
#pragma unroll
            for (int i2 = 0; i2 < 4; ++i2)
#pragma unroll
                for (int j = 0; j < 8; ++j)
#pragma unroll
                    for (int q = 0; q < 4; ++q) acc[i2][j][q] = 0.f;
            seg_first = 0u;
        }
    }
}

// ---------------------------------------------------------- launch
extern "C" void kernel_launch(void* const* d_in, const int* in_sizes, int n_in,
                              void* d_out, int out_size) {
    const float* x    = (const float*)d_in[0];
    const int*   wq   = (const int*)d_in[1];
    const float* sw   = (const float*)d_in[2];
    const int*   perm = (const int*)d_in[3];   // int32 or int64 — detected on device
    const float* bias = (const float*)d_in[4];
    float* out = (float*)d_out;

    int nsm = 148;
    cudaDeviceGetAttribute(&nsm, cudaDevAttrMultiProcessorCount, 0);
    const int ncta = 2 * nsm;                  // 2 CTAs per SM

    prep_kernel<<<4096 + MTOT + (ncta - 1), 256>>>(wq, sw, x, perm, bias, out, ncta);

    cudaFuncSetAttribute(gemm_kernel, cudaFuncAttributeMaxDynamicSharedMemorySize, GEMM_SMEM);
    gemm_kernel<<<ncta, 128, GEMM_SMEM>>>(bias, out, ncta);
}

// round 14
// speedup vs baseline: 1.6502x; 1.0038x over previous
#include <cuda_runtime.h>
#include <cuda_fp16.h>
#include <cstdint>

#define IN_F  4096
#define OUT_F 4096
#define MTOT  2048
#define NGRP  32          // IN_F / 128

// fp16 scratch (device globals: no allocation in kernel_launch)
__device__ __half g_wh[(size_t)OUT_F * IN_F];   // w_q * s_w, [o, k] K-major
__device__ __half g_xh[(size_t)MTOT  * IN_F];   // permuted x, [m, k] K-major

// Tile 128(M) x 128(N), BK = 64. 16 m-tiles x 32 n-tiles = 512 tiles x 64 k-iters.
static constexpr uint32_t TOTAL_CHUNKS = 32768u;
static constexpr uint32_t A_BYTES      = 16384;       // A 16KB + B 16KB per stage
static constexpr uint32_t STAGE_BYTES  = 32768;
static constexpr uint32_t GEMM_SMEM    = 3 * STAGE_BYTES;   // 96KB -> 2 CTAs/SM

// ------------------------------------------------------------------ helpers
__device__ __forceinline__ uint32_t smem_u32(const void* p) {
    uint32_t a;
    asm("{ .reg .u64 t; cvta.to.shared.u64 t, %1; cvt.u32.u64 %0, t; }" : "=r"(a) : "l"(p));
    return a;
}
__device__ __forceinline__ uint32_t sw128(uint32_t off) { return off ^ ((off >> 3) & 0x70); }
__device__ __forceinline__ void cpa16(uint32_t dst, const void* src) {
    asm volatile("cp.async.cg.shared.global [%0], [%1], 16;" :: "r"(dst), "l"(src));
}
__device__ __forceinline__ void redadd(float* p, float v) {
    asm volatile("red.global.add.f32 [%0], %1;" :: "l"(p), "f"(v) : "memory");
}
#define LDSM4(r0, r1, r2, r3, addr) \
    asm volatile("ldmatrix.sync.aligned.m8n8.x4.shared.b16 {%0,%1,%2,%3}, [%4];" \
        : "=r"(r0), "=r"(r1), "=r"(r2), "=r"(r3) : "r"(addr))
#define MMA16816(d0, d1, d2, d3, a0, a1, a2, a3, b0, b1) \
    asm volatile("mma.sync.aligned.m16n8k16.row.col.f32.f16.f16.f32 " \
        "{%0,%1,%2,%3},{%4,%5,%6,%7},{%8,%9},{%0,%1,%2,%3};" \
        : "+f"(d0), "+f"(d1), "+f"(d2), "+f"(d3) \
        : "r"(a0), "r"(a1), "r"(a2), "r"(a3), "r"(b0), "r"(b1))

// ---------------------------------------------------------- fused prep
// blocks [0, 4096):       w-row o; w_q * s_w -> fp16 (no smem staging)
// blocks [4096, 6144):    x-row m; permute + fp32->fp16
// blocks [6144, ...):     boundary c = bid-6144+1; prefill bias into SPLIT tiles only
__global__ void __launch_bounds__(256) prep_kernel(const int* __restrict__ wq,
                                                   const float* __restrict__ sw,
                                                   const float* __restrict__ x,
                                                   const int* __restrict__ perm32,
                                                   const float* __restrict__ bias,
                                                   float* __restrict__ out,
                                                   int ncta_) {
    __shared__ float row[IN_F];
    __shared__ int is64s;
    const int tid = threadIdx.x;
    const uint32_t ncta = (uint32_t)ncta_;

    if (blockIdx.x >= 6144) {            // split-tile bias prefill (128x128 tiles)
        const uint32_t c = blockIdx.x - 6144u + 1u;
        const uint32_t s = (c * TOTAL_CHUNKS) / ncta;
        if ((s & 63u) == 0u) return;
        const uint32_t t = s >> 6;
        const int m0 = (int)(t >> 5) * 128, n0 = (int)(t & 31u) * 128;
        if (tid < 128) row[tid] = bias[n0 + tid];
        __syncthreads();
#pragma unroll 4
        for (int it = 0; it < 16; ++it) {                 // 128 rows x 32 float4
            int idx = tid + it * 256;
            int r = idx >> 5, c4 = idx & 31;
            float4 v = make_float4(row[c4 * 4], row[c4 * 4 + 1], row[c4 * 4 + 2], row[c4 * 4 + 3]);
            __stcs(reinterpret_cast<float4*>(out + (size_t)(m0 + r) * OUT_F + n0) + c4, v);
        }
        return;
    }

    if (blockIdx.x < 4096) {
        const int o = blockIdx.x;
        const float s = __ldg(sw + (tid >> 3) * OUT_F + o);   // 8-thread broadcast
        const int k0 = tid * 16;
        const int4* p = reinterpret_cast<const int4*>(wq + (size_t)o * IN_F + k0);
        int4 w0 = __ldcs(p), w1 = __ldcs(p + 1), w2 = __ldcs(p + 2), w3 = __ldcs(p + 3);
        uint4 v0, v1;
        {
            __half2 h0 = __floats2half2_rn(w0.x * s, w0.y * s);
            __half2 h1 = __floats2half2_rn(w0.z * s, w0.w * s);
            __half2 h2 = __floats2half2_rn(w1.x * s, w1.y * s);
            __half2 h3 = __floats2half2_rn(w1.z * s, w1.w * s);
            v0.x = *reinterpret_cast<uint32_t*>(&h0);
            v0.y = *reinterpret_cast<uint32_t*>(&h1);
            v0.z = *reinterpret_cast<uint32_t*>(&h2);
            v0.w = *reinterpret_cast<uint32_t*>(&h3);
        }
        {
            __half2 h0 = __floats2half2_rn(w2.x * s, w2.y * s);
            __half2 h1 = __floats2half2_rn(w2.z * s, w2.w * s);
            __half2 h2 = __floats2half2_rn(w3.x * s, w3.y * s);
            __half2 h3 = __floats2half2_rn(w3.z * s, w3.w * s);
            v1.x = *reinterpret_cast<uint32_t*>(&h0);
            v1.y = *reinterpret_cast<uint32_t*>(&h1);
            v1.z = *reinterpret_cast<uint32_t*>(&h2);
            v1.w = *reinterpret_cast<uint32_t*>(&h3);
        }
        uint4* dst = reinterpret_cast<uint4*>(g_wh + (size_t)o * IN_F + k0);
        __stcs(dst, v0);
        __stcs(dst + 1, v1);
        return;
    }

    const int m = blockIdx.x - 4096;
    const float4* src = reinterpret_cast<const float4*>(x + (size_t)m * IN_F);
#pragma unroll
    for (int i = 0; i < 4; ++i)
        reinterpret_cast<float4*>(row)[tid + i * 256] = __ldcs(src + tid + i * 256);
    if (tid == 0) {
        // jnp int64 vs int32 detection: int64 LE => odd 32-bit words all zero.
        int acc = 0;
#pragma unroll
        for (int t = 1; t < 32; t += 2) acc |= perm32[t];
        is64s = (acc == 0) ? 1 : 0;
    }
    __syncthreads();
    const int sh = is64s;
    const int j0 = tid * 16;
    __half* dst = g_xh + (size_t)m * IN_F + j0;
#pragma unroll
    for (int h = 0; h < 2; ++h) {
        int jb = j0 + h * 8;
        float v[8];
#pragma unroll
        for (int i = 0; i < 8; ++i) v[i] = row[perm32[(jb + i) << sh]];
        __half2 p0 = __floats2half2_rn(v[0], v[1]);
        __half2 p1 = __floats2half2_rn(v[2], v[3]);
        __half2 p2 = __floats2half2_rn(v[4], v[5]);
        __half2 p3 = __floats2half2_rn(v[6], v[7]);
        uint4 u;
        u.x = *reinterpret_cast<uint32_t*>(&p0);
        u.y = *reinterpret_cast<uint32_t*>(&p1);
        u.z = *reinterpret_cast<uint32_t*>(&p2);
        u.w = *reinterpret_cast<uint32_t*>(&p3);
        __stcs(reinterpret_cast<uint4*>(dst + h * 8), u);
    }
}

// ---------------------------------------------------------- GEMM: persistent, 2 CTAs/SM
__device__ __forceinline__ void load_chunk(uint32_t sb, uint32_t chunk, int tid) {
    const uint32_t t = chunk >> 6;
    const int m0 = (int)(t >> 5) * 128;
    const int n0 = (int)(t & 31u) * 128;
    const int k0 = (int)(chunk & 63u) * 64;
#pragma unroll
    for (int c = 0; c < 8; ++c) {                 // A: 128 rows x 8 chunks of 16B
        int idx = tid + c * 128;
        int row = idx >> 3, ch = idx & 7;
        cpa16(sb + sw128((uint32_t)row * 128u + (uint32_t)ch * 16u),
              g_xh + (size_t)(m0 + row) * IN_F + k0 + ch * 8);
    }
#pragma unroll
    for (int c = 0; c < 8; ++c) {                 // B: 128 rows x 8 chunks
        int idx = tid + c * 128;
        int row = idx >> 3, ch = idx & 7;
        cpa16(sb + A_BYTES + sw128((uint32_t)row * 128u + (uint32_t)ch * 16u),
              g_wh + (size_t)(n0 + row) * IN_F + k0 + ch * 8);
    }
}

__device__ __forceinline__ void frag_load(uint32_t sA, uint32_t sB, int s,
                                          int arow_l, int a_c, int brow_l, int b_c,
                                          int wm, int wn, uint32_t a[4][4], uint32_t b[4][4]) {
#pragma unroll
    for (int mi = 0; mi < 4; ++mi) {
        uint32_t off = (uint32_t)((wm * 64 + mi * 16 + arow_l) * 128 + (s * 2 + a_c) * 16);
        LDSM4(a[mi][0], a[mi][1], a[mi][2], a[mi][3], sA + sw128(off));
    }
#pragma unroll
    for (int nb = 0; nb < 4; ++nb) {
        uint32_t off = (uint32_t)((wn * 64 + nb * 16 + brow_l) * 128 + (s * 2 + b_c) * 16);
        LDSM4(b[nb][0], b[nb][1], b[nb][2], b[nb][3], sB + sw128(off));
    }
}

__device__ __forceinline__ void frag_mma(const uint32_t a[4][4], const uint32_t b[4][4],
                                         float acc[4][8][4]) {
#pragma unroll
    for (int mi = 0; mi < 4; ++mi)
#pragma unroll
        for (int ni = 0; ni < 8; ++ni) {
            uint32_t b0 = b[ni >> 1][(ni & 1) * 2];
            uint32_t b1 = b[ni >> 1][(ni & 1) * 2 + 1];
            MMA16816(acc[mi][ni][0], acc[mi][ni][1], acc[mi][ni][2], acc[mi][ni][3],
                     a[mi][0], a[mi][1], a[mi][2], a[mi][3], b0, b1);
        }
}

__global__ void __launch_bounds__(128, 2) gemm_kernel(const float* __restrict__ bias,
                                                      float* __restrict__ out,
                                                      int ncta_) {
    extern __shared__ char smem[];
    const uint32_t sbase = smem_u32(smem);
    const uint32_t ncta = (uint32_t)ncta_;
    const int tid  = threadIdx.x;
    const int lane = tid & 31, wid = tid >> 5;
    const int wm = wid & 1, wn = wid >> 1;        // 2 x 2 warp grid
    const int arow_l = (lane & 7) + ((lane >> 3) & 1) * 8;
    const int a_c    = lane >> 4;
    const int brow_l = (lane & 7) + ((lane >> 4) & 1) * 8;
    const int b_c    = (lane >> 3) & 1;

    const uint32_t cta = blockIdx.x;
    const uint32_t start = (cta * TOTAL_CHUNKS) / ncta;
    const uint32_t end   = ((cta + 1u) * TOTAL_CHUNKS) / ncta;

    float acc[4][8][4];
#pragma unroll
    for (int i = 0; i < 4; ++i)
#pragma unroll
        for (int j = 0; j < 8; ++j)
#pragma unroll
            for (int q = 0; q < 4; ++q) acc[i][j][q] = 0.f;

    uint32_t afrag[2][4][4], bfrag[2][4][4];
    uint32_t seg_first = start & 63u;

#if __CUDA_ARCH__ >= 900
    cudaGridDependencySynchronize();              // PDL: wait for prep outputs
#endif

    // prologue: chunks start, start+1 (slot = chunk % 3)
    load_chunk(sbase + (start % 3u) * STAGE_BYTES, start, tid);
    asm volatile("cp.async.commit_group;" ::: "memory");
    if (start + 1u < end)
        load_chunk(sbase + ((start + 1u) % 3u) * STAGE_BYTES, start + 1u, tid);
    asm volatile("cp.async.commit_group;" ::: "memory");

    for (uint32_t ch = start; ch < end; ++ch) {
        asm volatile("cp.async.wait_group 1;" ::: "memory");
        __syncthreads();

        const uint32_t sA = sbase + (ch % 3u) * STAGE_BYTES;
        const uint32_t sB = sA + A_BYTES;

        // Step-0 fragments FIRST, so they aren't queued behind the LDGSTS burst.
        frag_load(sA, sB, 0, arow_l, a_c, brow_l, b_c, wm, wn, afrag[0], bfrag[0]);

        if (ch + 2u < end)
            load_chunk(sbase + ((ch + 2u) % 3u) * STAGE_BYTES, ch + 2u, tid);
        asm volatile("cp.async.commit_group;" ::: "memory");

#pragma unroll
        for (int s = 0; s < 4; ++s) {
            if (s < 3)
                frag_load(sA, sB, s + 1, arow_l, a_c, brow_l, b_c, wm, wn,
                          afrag[(s + 1) & 1], bfrag[(s + 1) & 1]);
            frag_mma(afrag[s & 1], bfrag[s & 1], acc);
        }

        const uint32_t kidx = ch & 63u;
        const bool tile_done = (kidx == 63u) || (ch + 1u == end);
        if (tile_done) {
            const uint32_t t = ch >> 6;
            const int n0 = (int)(t & 31u) * 128;
            const int m0 = (int)(t >> 5) * 128;
            const int ncol = n0 + wn * 64 + (lane & 3) * 2;
            const int mrow = m0 + wm * 64 + (lane >> 2);
            const bool full = (seg_first == 0u && kidx == 63u);
            if (full) {                           // sole writer: direct store with bias
#pragma unroll
                for (int mi = 0; mi < 4; ++mi) {
                    float* r0 = out + (size_t)(mrow + mi * 16) * OUT_F;
                    float* r1 = r0 + 8 * OUT_F;
#pragma unroll
                    for (int ni = 0; ni < 8; ++ni) {
                        float2 bv = *reinterpret_cast<const float2*>(bias + ncol + ni * 8);
                        float2 v0, v1;
                        v0.x = acc[mi][ni][0] + bv.x;
                        v0.y = acc[mi][ni][1] + bv.y;
                        v1.x = acc[mi][ni][2] + bv.x;
                        v1.y = acc[mi][ni][3] + bv.y;
                        __stcs(reinterpret_cast<float2*>(r0 + ncol + ni * 8), v0);
                        __stcs(reinterpret_cast<float2*>(r1 + ncol + ni * 8), v1);
                    }
                }
            } else {                              // split tile: accumulate into prefilled out
#pragma unroll
                for (int mi = 0; mi < 4; ++mi) {
                    float* r0 = out + (size_t)(mrow + mi * 16) * OUT_F;
                    float* r1 = r0 + 8 * OUT_F;
#pragma unroll
                    for (int ni = 0; ni < 8; ++ni) {
                        redadd(r0 + ncol + ni * 8,     acc[mi][ni][0]);
                        redadd(r0 + ncol + ni * 8 + 1, acc[mi][ni][1]);
                        redadd(r1 + ncol + ni * 8,     acc[mi][ni][2]);
                        redadd(r1 + ncol + ni * 8 + 1, acc[mi][ni][3]);
                    }
                }
            }
#pragma unroll
            for (int i2 = 0; i2 < 4; ++i2)
#pragma unroll
                for (int j = 0; j < 8; ++j)
#pragma unroll
                    for (int q = 0; q < 4; ++q) acc[i2][j][q] = 0.f;
            seg_first = 0u;
        }
    }
}

// ---------------------------------------------------------- launch
extern "C" void kernel_launch(void* const* d_in, const int* in_sizes, int n_in,
                              void* d_out, int out_size) {
    const float* x    = (const float*)d_in[0];
    const int*   wq   = (const int*)d_in[1];
    const float* sw   = (const float*)d_in[2];
    const int*   perm = (const int*)d_in[3];   // int32 or int64 — detected on device
    const float* bias = (const float*)d_in[4];
    float* out = (float*)d_out;

    int nsm = 148;
    cudaDeviceGetAttribute(&nsm, cudaDevAttrMultiProcessorCount, 0);
    const int ncta = 2 * nsm;                  // 2 CTAs per SM

    prep_kernel<<<4096 + MTOT + (ncta - 1), 256>>>(wq, sw, x, perm, bias, out, ncta);

    cudaFuncSetAttribute(gemm_kernel, cudaFuncAttributeMaxDynamicSharedMemorySize, GEMM_SMEM);

    // PDL launch: GEMM starts while prep drains; gemm_kernel gates on
    // cudaGridDependencySynchronize() before touching prep outputs.
    cudaLaunchConfig_t cfg = {};
    cfg.gridDim  = dim3((unsigned)ncta, 1, 1);
    cfg.blockDim = dim3(128, 1, 1);
    cfg.dynamicSmemBytes = GEMM_SMEM;
    cudaLaunchAttribute attrs[1];
    attrs[0].id = cudaLaunchAttributeProgrammaticStreamSerialization;
    attrs[0].val.programmaticStreamSerializationAllowed = 1;
    cfg.attrs = attrs;
    cfg.numAttrs = 1;
    cudaError_t err = cudaLaunchKernelEx(&cfg, gemm_kernel, bias, out, ncta);
    if (err != cudaSuccess) {                  // fallback: plain serialized launch
        gemm_kernel<<<ncta, 128, GEMM_SMEM>>>(bias, out, ncta);
    }
}